// round 2
// baseline (speedup 1.0000x reference)
#include <cuda_runtime.h>
#include <math.h>

#define SEQT 2048
#define INSZ 512
#define HID  1024
#define G4   4096   // 4*HID
#define OUTD 4

// ---------------- scratch (static device allocations only) ----------------
__device__ float g_gx[SEQT * G4];     // 32 MB: input projections + biases
__device__ float g_ys[SEQT * HID];    // 8 MB: LSTM outputs
__device__ float g_h1[SEQT * HID];    // 8 MB
__device__ float g_h2[SEQT * HID];    // 8 MB
__device__ float g_hbuf[2][HID];      // double-buffered recurrent state
__device__ unsigned g_count;          // zero-init; self-resets each barrier
__device__ unsigned g_gen;            // monotonically increasing generation

// ---------------- tiled SGEMM: C[M,N] = A[M,K] @ B[N,K]^T + bias (+bias2), opt ReLU
// M,N % 64 == 0, K % 16 == 0. 256 threads, 64x64 tile, 4x4 per thread.
__global__ void __launch_bounds__(256) sgemm_bt(
    const float* __restrict__ A, const float* __restrict__ B,
    const float* __restrict__ bias, const float* __restrict__ bias2,
    float* __restrict__ C, int M, int N, int K, int relu)
{
    __shared__ float As[16][64];
    __shared__ float Bs[16][64];
    int tid = threadIdx.x;
    int tx = tid & 15, ty = tid >> 4;
    int m0 = blockIdx.y * 64, n0 = blockIdx.x * 64;

    int lm  = tid >> 2;   // 0..63 tile row for loads
    int lk4 = tid & 3;    // 0..3 float4 within 16-wide k chunk

    const float4* Ag = (const float4*)(A + (size_t)(m0 + lm) * K) + lk4;
    const float4* Bg = (const float4*)(B + (size_t)(n0 + lm) * K) + lk4;

    float acc[4][4] = {};

    for (int k0 = 0; k0 < K; k0 += 16) {
        float4 av = *Ag; Ag += 4;
        float4 bv = *Bg; Bg += 4;
        __syncthreads();
        As[lk4 * 4 + 0][lm] = av.x; As[lk4 * 4 + 1][lm] = av.y;
        As[lk4 * 4 + 2][lm] = av.z; As[lk4 * 4 + 3][lm] = av.w;
        Bs[lk4 * 4 + 0][lm] = bv.x; Bs[lk4 * 4 + 1][lm] = bv.y;
        Bs[lk4 * 4 + 2][lm] = bv.z; Bs[lk4 * 4 + 3][lm] = bv.w;
        __syncthreads();
        #pragma unroll
        for (int k = 0; k < 16; k++) {
            float4 a4 = *(const float4*)&As[k][ty * 4];
            float4 b4 = *(const float4*)&Bs[k][tx * 4];
            float a_[4] = {a4.x, a4.y, a4.z, a4.w};
            float b_[4] = {b4.x, b4.y, b4.z, b4.w};
            #pragma unroll
            for (int i = 0; i < 4; i++)
                #pragma unroll
                for (int j = 0; j < 4; j++)
                    acc[i][j] = fmaf(a_[i], b_[j], acc[i][j]);
        }
    }

    int n = n0 + tx * 4;
    float bb[4];
    #pragma unroll
    for (int j = 0; j < 4; j++) {
        bb[j] = bias ? bias[n + j] : 0.f;
        if (bias2) bb[j] += bias2[n + j];
    }
    #pragma unroll
    for (int i = 0; i < 4; i++) {
        int m = m0 + ty * 4 + i;
        float4 r;
        r.x = acc[i][0] + bb[0];
        r.y = acc[i][1] + bb[1];
        r.z = acc[i][2] + bb[2];
        r.w = acc[i][3] + bb[3];
        if (relu) {
            r.x = fmaxf(r.x, 0.f); r.y = fmaxf(r.y, 0.f);
            r.z = fmaxf(r.z, 0.f); r.w = fmaxf(r.w, 0.f);
        }
        *(float4*)&C[(size_t)m * N + n] = r;
    }
}

// ---------------- grid barrier (sense via monotonically increasing generation)
__device__ __forceinline__ void grid_barrier(int nblocks)
{
    __syncthreads();
    if (threadIdx.x == 0) {
        unsigned gen = *(volatile unsigned*)&g_gen;
        __threadfence();                       // release my writes
        unsigned v = atomicAdd(&g_count, 1u);
        if (v == (unsigned)nblocks - 1u) {
            g_count = 0u;
            __threadfence();                   // reset visible before release
            *(volatile unsigned*)&g_gen = gen + 1u;
        } else {
            while (*(volatile unsigned*)&g_gen == gen) { __nanosleep(64); }
        }
        __threadfence();                       // acquire
    }
    __syncthreads();
}

__device__ __forceinline__ float sigmoidf_(float x) { return 1.f / (1.f + __expf(-x)); }

// ---------------- persistent LSTM recurrence ----------------
// grid = 128 blocks x 256 threads. Block b owns hidden units [8b, 8b+8).
// Warp w handles hidden unit hu = 8b + w; lane layout: gate = lane>>3, kofs = lane&7.
#define LSTM_BLOCKS 128
__global__ void __launch_bounds__(256, 1) lstm_kernel(
    const float* __restrict__ gx, const float* __restrict__ w_hh,
    const float* __restrict__ h0, const float* __restrict__ c0,
    float* __restrict__ ys, float* __restrict__ out)
{
    __shared__ float sh[HID];
    int tid  = threadIdx.x;
    int warp = tid >> 5, lane = tid & 31;
    int hu   = blockIdx.x * 8 + warp;          // 0..1023
    int gate = lane >> 3;                      // 0..3 (i,f,g,o)
    int kofs = lane & 7;                       // 0..7

    const float4* wrow = (const float4*)(w_hh + ((size_t)(gate * HID + hu)) * HID) + kofs;

    // init state
    float c = c0[hu];
    float hlast = h0[hu];
    if (blockIdx.x == 0)
        for (int i = tid; i < HID; i += 256) g_hbuf[0][i] = h0[i];
    grid_barrier(LSTM_BLOCKS);

    for (int t = 0; t < SEQT; t++) {
        const float* hb  = g_hbuf[t & 1];
        float*       hbn = g_hbuf[(t & 1) ^ 1];

        // stage current h into shared (L2-coherent load)
        float4 hv = __ldcg((const float4*)hb + tid);
        ((float4*)sh)[tid] = hv;
        __syncthreads();

        // dot(w_hh[row], h): 8 lanes per row, each 128 elems (32 float4)
        float acc = 0.f;
        const float4* h4 = (const float4*)sh;
        #pragma unroll 8
        for (int i = 0; i < 32; i++) {
            float4 w4 = __ldg(wrow + (i << 3));
            float4 x4 = h4[kofs + (i << 3)];
            acc = fmaf(w4.x, x4.x, acc);
            acc = fmaf(w4.y, x4.y, acc);
            acc = fmaf(w4.z, x4.z, acc);
            acc = fmaf(w4.w, x4.w, acc);
        }
        acc += __shfl_down_sync(0xffffffffu, acc, 4);
        acc += __shfl_down_sync(0xffffffffu, acc, 2);
        acc += __shfl_down_sync(0xffffffffu, acc, 1);

        float gval = 0.f;
        if (kofs == 0)
            gval = acc + __ldcs(&gx[(size_t)t * G4 + gate * HID + hu]);

        float gi = __shfl_sync(0xffffffffu, gval, 0);
        float gf = __shfl_sync(0xffffffffu, gval, 8);
        float gg = __shfl_sync(0xffffffffu, gval, 16);
        float go = __shfl_sync(0xffffffffu, gval, 24);

        float i_ = sigmoidf_(gi);
        float f_ = sigmoidf_(gf);
        float g_ = tanhf(gg);
        float o_ = sigmoidf_(go);
        c = fmaf(f_, c, i_ * g_);
        float h = o_ * tanhf(c);
        hlast = h;

        if (lane == 0) {
            __stcg(&hbn[hu], h);
            __stcs(&ys[(size_t)t * HID + hu], h);
        }
        grid_barrier(LSTM_BLOCKS);
    }

    // hT at out[16384..17407], cT at out[17408..18431]
    if (lane == 0) {
        out[2 * SEQT * OUTD + hu] = hlast;
        out[2 * SEQT * OUTD + HID + hu] = c;
    }
}

// ---------------- policy head: mean = h2 @ mean_w^T + mean_b; log_std broadcast
__global__ void __launch_bounds__(128) head_kernel(
    const float* __restrict__ h2, const float* __restrict__ mean_w,
    const float* __restrict__ mean_b, const float* __restrict__ log_std,
    float* __restrict__ out)
{
    __shared__ float sh[HID];
    int t = blockIdx.x;
    for (int i = threadIdx.x; i < HID; i += 128) sh[i] = h2[(size_t)t * HID + i];
    __syncthreads();
    int w = threadIdx.x >> 5, lane = threadIdx.x & 31;
    const float* wr = mean_w + (size_t)w * HID;
    float acc = 0.f;
    for (int k = lane; k < HID; k += 32) acc = fmaf(wr[k], sh[k], acc);
    #pragma unroll
    for (int o = 16; o; o >>= 1) acc += __shfl_down_sync(0xffffffffu, acc, o);
    if (lane == 0) {
        out[(size_t)t * OUTD + w] = acc + mean_b[w];
        out[SEQT * OUTD + (size_t)t * OUTD + w] = log_std[w];
    }
}

// ---------------- launcher ----------------
extern "C" void kernel_launch(void* const* d_in, const int* in_sizes, int n_in,
                              void* d_out, int out_size)
{
    const float* x      = (const float*)d_in[0];
    const float* h0     = (const float*)d_in[1];
    const float* c0     = (const float*)d_in[2];
    const float* w_ih   = (const float*)d_in[3];
    const float* w_hh   = (const float*)d_in[4];
    const float* b_ih   = (const float*)d_in[5];
    const float* b_hh   = (const float*)d_in[6];
    const float* fc1_w  = (const float*)d_in[7];
    const float* fc1_b  = (const float*)d_in[8];
    const float* fc2_w  = (const float*)d_in[9];
    const float* fc2_b  = (const float*)d_in[10];
    const float* mean_w = (const float*)d_in[11];
    const float* mean_b = (const float*)d_in[12];
    const float* lstd   = (const float*)d_in[13];
    float* out = (float*)d_out;

    float *gx, *ys, *h1, *h2;
    cudaGetSymbolAddress((void**)&gx, g_gx);
    cudaGetSymbolAddress((void**)&ys, g_ys);
    cudaGetSymbolAddress((void**)&h1, g_h1);
    cudaGetSymbolAddress((void**)&h2, g_h2);

    // gx = x @ w_ih^T + b_ih + b_hh : [2048, 4096]
    sgemm_bt<<<dim3(G4 / 64, SEQT / 64), 256>>>(x, w_ih, b_ih, b_hh, gx,
                                                SEQT, G4, INSZ, 0);
    // recurrence (persistent; also writes hT, cT into out)
    lstm_kernel<<<LSTM_BLOCKS, 256>>>(gx, w_hh, h0, c0, ys, out);
    // fc1, fc2 with ReLU
    sgemm_bt<<<dim3(HID / 64, SEQT / 64), 256>>>(ys, fc1_w, fc1_b, nullptr, h1,
                                                 SEQT, HID, HID, 1);
    sgemm_bt<<<dim3(HID / 64, SEQT / 64), 256>>>(h1, fc2_w, fc2_b, nullptr, h2,
                                                 SEQT, HID, HID, 1);
    // head: action_mean + action_log_std
    head_kernel<<<SEQT, 128>>>(h2, mean_w, mean_b, lstd, out);
}

// round 5
// speedup vs baseline: 1.4106x; 1.4106x over previous
#include <cuda_runtime.h>
#include <math.h>

#define SEQT 2048
#define INSZ 512
#define HID  1024
#define G4   4096   // 4*HID
#define OUTD 4

// ---------------- scratch (static device allocations only) ----------------
__device__ float g_gx[SEQT * G4];     // 32 MB: input projections + biases
__device__ float g_ys[SEQT * HID];    // 8 MB: LSTM outputs
__device__ float g_h1[SEQT * HID];    // 8 MB
__device__ float g_h2[SEQT * HID];    // 8 MB
__device__ float g_hbuf[2][HID];      // double-buffered recurrent state
__device__ unsigned g_arrive;         // monotonic arrival counter (reset by reset_kernel)

// ---------------- tiled SGEMM: C[M,N] = A[M,K] @ B[N,K]^T + bias (+bias2), opt ReLU
__global__ void __launch_bounds__(256) sgemm_bt(
    const float* __restrict__ A, const float* __restrict__ B,
    const float* __restrict__ bias, const float* __restrict__ bias2,
    float* __restrict__ C, int M, int N, int K, int relu)
{
    __shared__ float As[16][64];
    __shared__ float Bs[16][64];
    int tid = threadIdx.x;
    int tx = tid & 15, ty = tid >> 4;
    int m0 = blockIdx.y * 64, n0 = blockIdx.x * 64;

    int lm  = tid >> 2;
    int lk4 = tid & 3;

    const float4* Ag = (const float4*)(A + (size_t)(m0 + lm) * K) + lk4;
    const float4* Bg = (const float4*)(B + (size_t)(n0 + lm) * K) + lk4;

    float acc[4][4] = {};

    for (int k0 = 0; k0 < K; k0 += 16) {
        float4 av = *Ag; Ag += 4;
        float4 bv = *Bg; Bg += 4;
        __syncthreads();
        As[lk4 * 4 + 0][lm] = av.x; As[lk4 * 4 + 1][lm] = av.y;
        As[lk4 * 4 + 2][lm] = av.z; As[lk4 * 4 + 3][lm] = av.w;
        Bs[lk4 * 4 + 0][lm] = bv.x; Bs[lk4 * 4 + 1][lm] = bv.y;
        Bs[lk4 * 4 + 2][lm] = bv.z; Bs[lk4 * 4 + 3][lm] = bv.w;
        __syncthreads();
        #pragma unroll
        for (int k = 0; k < 16; k++) {
            float4 a4 = *(const float4*)&As[k][ty * 4];
            float4 b4 = *(const float4*)&Bs[k][tx * 4];
            float a_[4] = {a4.x, a4.y, a4.z, a4.w};
            float b_[4] = {b4.x, b4.y, b4.z, b4.w};
            #pragma unroll
            for (int i = 0; i < 4; i++)
                #pragma unroll
                for (int j = 0; j < 4; j++)
                    acc[i][j] = fmaf(a_[i], b_[j], acc[i][j]);
        }
    }

    int n = n0 + tx * 4;
    float bb[4];
    #pragma unroll
    for (int j = 0; j < 4; j++) {
        bb[j] = bias ? bias[n + j] : 0.f;
        if (bias2) bb[j] += bias2[n + j];
    }
    #pragma unroll
    for (int i = 0; i < 4; i++) {
        int m = m0 + ty * 4 + i;
        float4 r;
        r.x = acc[i][0] + bb[0];
        r.y = acc[i][1] + bb[1];
        r.z = acc[i][2] + bb[2];
        r.w = acc[i][3] + bb[3];
        if (relu) {
            r.x = fmaxf(r.x, 0.f); r.y = fmaxf(r.y, 0.f);
            r.z = fmaxf(r.z, 0.f); r.w = fmaxf(r.w, 0.f);
        }
        *(float4*)&C[(size_t)m * N + n] = r;
    }
}

// ---------------- sync helpers ----------------
__device__ __forceinline__ unsigned ld_acq_gpu(const unsigned* p)
{
    unsigned v;
    asm volatile("ld.acquire.gpu.global.u32 %0, [%1];" : "=r"(v) : "l"(p) : "memory");
    return v;
}

__device__ __forceinline__ float tanh_approx(float x)
{
    float r;
    asm("tanh.approx.f32 %0, %1;" : "=f"(r) : "f"(x));
    return r;
}

__device__ __forceinline__ float sigmoidf_(float x) { return 1.f / (1.f + __expf(-x)); }

__global__ void reset_kernel() { g_arrive = 0u; }

// ---------------- persistent LSTM recurrence ----------------
// grid = 128 blocks x 256 threads. Block b owns hidden units [8b, 8b+8).
// Warp w handles hidden unit hu = 8b + w; lane layout: gate = lane>>3, kofs = lane&7.
// Arrival protocol: after writing its h-slice for step t (init counts as t=-1 producer),
// each block bumps g_arrive; reading h for step t requires g_arrive >= 128*(t+1).
#define LSTM_BLOCKS 128
__global__ void __launch_bounds__(256, 1) lstm_kernel(
    const float* __restrict__ gx, const float* __restrict__ w_hh,
    const float* __restrict__ h0, const float* __restrict__ c0,
    float* __restrict__ ys, float* __restrict__ out)
{
    __shared__ float sh[HID];
    int tid  = threadIdx.x;
    int warp = tid >> 5, lane = tid & 31;
    int hu   = blockIdx.x * 8 + warp;          // 0..1023
    int gate = lane >> 3;                      // 0..3 (i,f,g,o)
    int kofs = lane & 7;                       // 0..7

    const float4* wrow = (const float4*)(w_hh + ((size_t)(gate * HID + hu)) * HID) + kofs;
    const float*  gxp  = gx + gate * HID + hu;

    // init state; this block produces its slice of h(0) buffer
    float c = c0[hu];
    float hlast = h0[hu];
    if (lane == 0) __stcg(&g_hbuf[0][hu], hlast);
    __syncthreads();
    if (tid == 0) {
        __threadfence();
        atomicAdd(&g_arrive, 1u);
    }

    for (int t = 0; t < SEQT; t++) {
        const float4* hb  = (const float4*)g_hbuf[t & 1];
        float*        hbn = g_hbuf[(t & 1) ^ 1];

        // prefetch gx for this step (independent of other blocks)
        float gxv = 0.f;
        if (kofs == 0) gxv = __ldcs(gxp + (size_t)t * G4);

        // wait until all 128 blocks produced h(t)
        if (tid == 0) {
            unsigned target = (unsigned)(LSTM_BLOCKS * (t + 1));
            while (ld_acq_gpu(&g_arrive) < target) { }
        }
        __syncthreads();

        // stage current h into shared (L2-coherent load)
        float4 hv = __ldcg(hb + tid);
        ((float4*)sh)[tid] = hv;
        __syncthreads();

        // dot(w_hh[row], h): 8 lanes per row, each 128 elems (32 float4),
        // 4 independent accumulators to break the FMA RAW chain.
        float a0 = 0.f, a1 = 0.f, a2 = 0.f, a3 = 0.f;
        const float4* h4 = (const float4*)sh;
        #pragma unroll
        for (int i = 0; i < 32; i += 4) {
            float4 w0 = __ldg(wrow + ((i + 0) << 3));
            float4 x0 = h4[kofs + ((i + 0) << 3)];
            float4 w1 = __ldg(wrow + ((i + 1) << 3));
            float4 x1 = h4[kofs + ((i + 1) << 3)];
            float4 w2 = __ldg(wrow + ((i + 2) << 3));
            float4 x2 = h4[kofs + ((i + 2) << 3)];
            float4 w3 = __ldg(wrow + ((i + 3) << 3));
            float4 x3 = h4[kofs + ((i + 3) << 3)];
            a0 = fmaf(w0.x, x0.x, a0); a0 = fmaf(w0.y, x0.y, a0);
            a0 = fmaf(w0.z, x0.z, a0); a0 = fmaf(w0.w, x0.w, a0);
            a1 = fmaf(w1.x, x1.x, a1); a1 = fmaf(w1.y, x1.y, a1);
            a1 = fmaf(w1.z, x1.z, a1); a1 = fmaf(w1.w, x1.w, a1);
            a2 = fmaf(w2.x, x2.x, a2); a2 = fmaf(w2.y, x2.y, a2);
            a2 = fmaf(w2.z, x2.z, a2); a2 = fmaf(w2.w, x2.w, a2);
            a3 = fmaf(w3.x, x3.x, a3); a3 = fmaf(w3.y, x3.y, a3);
            a3 = fmaf(w3.z, x3.z, a3); a3 = fmaf(w3.w, x3.w, a3);
        }
        float acc = (a0 + a1) + (a2 + a3);
        acc += __shfl_down_sync(0xffffffffu, acc, 4);
        acc += __shfl_down_sync(0xffffffffu, acc, 2);
        acc += __shfl_down_sync(0xffffffffu, acc, 1);

        float gval = acc + gxv;                  // only meaningful on kofs==0 lanes

        float gi = __shfl_sync(0xffffffffu, gval, 0);
        float gf = __shfl_sync(0xffffffffu, gval, 8);
        float gg = __shfl_sync(0xffffffffu, gval, 16);
        float go = __shfl_sync(0xffffffffu, gval, 24);

        float i_ = sigmoidf_(gi);
        float f_ = sigmoidf_(gf);
        float g_ = tanh_approx(gg);
        float o_ = sigmoidf_(go);
        c = fmaf(f_, c, i_ * g_);
        float h = o_ * tanh_approx(c);
        hlast = h;

        if (lane == 0) {
            __stcg(&hbn[hu], h);
            __stcs(&ys[(size_t)t * HID + hu], h);
        }
        __syncthreads();
        if (tid == 0) {
            __threadfence();
            atomicAdd(&g_arrive, 1u);
        }
    }

    // hT at out[16384..17407], cT at out[17408..18431]
    if (lane == 0) {
        out[2 * SEQT * OUTD + hu] = hlast;
        out[2 * SEQT * OUTD + HID + hu] = c;
    }
}

// ---------------- policy head ----------------
__global__ void __launch_bounds__(128) head_kernel(
    const float* __restrict__ h2, const float* __restrict__ mean_w,
    const float* __restrict__ mean_b, const float* __restrict__ log_std,
    float* __restrict__ out)
{
    __shared__ float sh[HID];
    int t = blockIdx.x;
    for (int i = threadIdx.x; i < HID; i += 128) sh[i] = h2[(size_t)t * HID + i];
    __syncthreads();
    int w = threadIdx.x >> 5, lane = threadIdx.x & 31;
    const float* wr = mean_w + (size_t)w * HID;
    float acc = 0.f;
    for (int k = lane; k < HID; k += 32) acc = fmaf(wr[k], sh[k], acc);
    #pragma unroll
    for (int o = 16; o; o >>= 1) acc += __shfl_down_sync(0xffffffffu, acc, o);
    if (lane == 0) {
        out[(size_t)t * OUTD + w] = acc + mean_b[w];
        out[SEQT * OUTD + (size_t)t * OUTD + w] = log_std[w];
    }
}

// ---------------- launcher ----------------
extern "C" void kernel_launch(void* const* d_in, const int* in_sizes, int n_in,
                              void* d_out, int out_size)
{
    const float* x      = (const float*)d_in[0];
    const float* h0     = (const float*)d_in[1];
    const float* c0     = (const float*)d_in[2];
    const float* w_ih   = (const float*)d_in[3];
    const float* w_hh   = (const float*)d_in[4];
    const float* b_ih   = (const float*)d_in[5];
    const float* b_hh   = (const float*)d_in[6];
    const float* fc1_w  = (const float*)d_in[7];
    const float* fc1_b  = (const float*)d_in[8];
    const float* fc2_w  = (const float*)d_in[9];
    const float* fc2_b  = (const float*)d_in[10];
    const float* mean_w = (const float*)d_in[11];
    const float* mean_b = (const float*)d_in[12];
    const float* lstd   = (const float*)d_in[13];
    float* out = (float*)d_out;

    float *gx, *ys, *h1, *h2;
    cudaGetSymbolAddress((void**)&gx, g_gx);
    cudaGetSymbolAddress((void**)&ys, g_ys);
    cudaGetSymbolAddress((void**)&h1, g_h1);
    cudaGetSymbolAddress((void**)&h2, g_h2);

    // gx = x @ w_ih^T + b_ih + b_hh : [2048, 4096]
    sgemm_bt<<<dim3(G4 / 64, SEQT / 64), 256>>>(x, w_ih, b_ih, b_hh, gx,
                                                SEQT, G4, INSZ, 0);
    // reset arrival counter (same stream: ordered, graph-capturable)
    reset_kernel<<<1, 1>>>();
    // recurrence (persistent; also writes hT, cT into out)
    lstm_kernel<<<LSTM_BLOCKS, 256>>>(gx, w_hh, h0, c0, ys, out);
    // fc1, fc2 with ReLU
    sgemm_bt<<<dim3(HID / 64, SEQT / 64), 256>>>(ys, fc1_w, fc1_b, nullptr, h1,
                                                 SEQT, HID, HID, 1);
    sgemm_bt<<<dim3(HID / 64, SEQT / 64), 256>>>(h1, fc2_w, fc2_b, nullptr, h2,
                                                 SEQT, HID, HID, 1);
    // head: action_mean + action_log_std
    head_kernel<<<SEQT, 128>>>(h2, mean_w, mean_b, lstd, out);
}